// round 12
// baseline (speedup 1.0000x reference)
#include <cuda_runtime.h>
#include <cuda_bf16.h>
#include <cuda_fp16.h>
#include <cstdint>

#define NCH   8
#define TOPK  2
#define BSZ   4096
#define INF   4096
#define CIN   512
#define COUT  512
#define HID   1024
#define OUTF  4096

// ---------------- device scratch (no allocations allowed) ----------------
__device__ float g_act[NCH];          // zero-initialized at load; topk re-zeros after use
__device__ int   g_topk[TOPK];

__device__ __half g_xh[(size_t)TOPK * BSZ * CIN];     // x selected, fp16 hi
__device__ __half g_xl[(size_t)TOPK * BSZ * CIN];     // x selected, fp16 lo
__device__ __half g_wc[(size_t)TOPK * COUT * CIN];    // W_chunk^T fp16 [N][K]
__device__ __half g_hh[(size_t)BSZ * HID];            // h fp16 hi
__device__ __half g_hl[(size_t)BSZ * HID];            // h fp16 lo
__device__ __half g_wf[(size_t)OUTF * HID];           // W_final^T fp16 [N][K]

// ---------------- routing ----------------
__global__ void activity_kernel(const float* __restrict__ x) {
    float local[NCH];
#pragma unroll
    for (int c = 0; c < NCH; c++) local[c] = 0.0f;
    const long long total = (long long)BSZ * INF;
    const long long stride = (long long)gridDim.x * blockDim.x * 4;
    for (long long i = ((long long)blockIdx.x * blockDim.x + threadIdx.x) * 4; i < total; i += stride) {
        float4 v = *reinterpret_cast<const float4*>(x + i);
        int c = (int)((i >> 9) & 7);
        local[c] += fabsf(v.x) + fabsf(v.y) + fabsf(v.z) + fabsf(v.w);
    }
    __shared__ float sred[NCH];
    if (threadIdx.x < NCH) sred[threadIdx.x] = 0.0f;
    __syncthreads();
#pragma unroll
    for (int c = 0; c < NCH; c++) {
        float v = local[c];
#pragma unroll
        for (int off = 16; off > 0; off >>= 1) v += __shfl_xor_sync(0xffffffffu, v, off);
        if ((threadIdx.x & 31) == 0) atomicAdd(&sred[c], v);
    }
    __syncthreads();
    if (threadIdx.x < NCH) atomicAdd(&g_act[threadIdx.x], sred[threadIdx.x]);
}

__global__ void topk_kernel() {
    int best = 0;
#pragma unroll
    for (int i = 1; i < NCH; i++)
        if (g_act[i] > g_act[best]) best = i;
    int second = (best == 0) ? 1 : 0;
#pragma unroll
    for (int i = 0; i < NCH; i++)
        if (i != best && g_act[i] > g_act[second]) second = i;
    g_topk[0] = best;
    g_topk[1] = second;
#pragma unroll
    for (int i = 0; i < NCH; i++) g_act[i] = 0.0f;
}

// ---------------- conversions ----------------
__device__ __forceinline__ void split2h(float v, __half& h, __half& l) {
    h = __float2half_rn(v);
    l = __float2half_rn(v - __half2float(h));
}

#define CVT_X_BLKS  4096
#define CVT_WC_BLKS 512
#define CVT_WF_BLKS 4096
#define CVT_TOTAL   (CVT_X_BLKS + CVT_WC_BLKS + CVT_WF_BLKS)

__global__ __launch_bounds__(256) void convert_all_kernel(
    const float* __restrict__ x,
    const float* __restrict__ Wc,
    const float* __restrict__ Wf)
{
    __shared__ float t[32][33];
    const int blk = blockIdx.x;

    if (blk < CVT_X_BLKS) {
        size_t g = (size_t)blk * 256 + threadIdx.x;
        int z = (int)(g >> 19);
        size_t r = g & 524287;
        int row = (int)(r >> 7);
        int c4  = (int)(r & 127);
        int chunk = g_topk[z];
        float4 v = __ldg((const float4*)(x + (size_t)row * INF + (size_t)chunk * CIN) + c4);
        __half h0, h1, h2, h3, l0, l1, l2, l3;
        split2h(v.x, h0, l0); split2h(v.y, h1, l1); split2h(v.z, h2, l2); split2h(v.w, h3, l3);
        size_t o = (size_t)z * BSZ * CIN + (size_t)row * CIN + (size_t)c4 * 4;
        *(ushort4*)(g_xh + o) = make_ushort4(__half_as_ushort(h0), __half_as_ushort(h1),
                                             __half_as_ushort(h2), __half_as_ushort(h3));
        *(ushort4*)(g_xl + o) = make_ushort4(__half_as_ushort(l0), __half_as_ushort(l1),
                                             __half_as_ushort(l2), __half_as_ushort(l3));
    } else if (blk < CVT_X_BLKS + CVT_WC_BLKS) {
        int idx = blk - CVT_X_BLKS;
        int z = idx >> 8, rem = idx & 255;
        int bx = rem & 15, by = rem >> 4;
        int tx = threadIdx.x & 31, ty = threadIdx.x >> 5;
        int chunk = g_topk[z];
        const float* W = Wc + (size_t)chunk * CIN * COUT;
#pragma unroll
        for (int i = 0; i < 4; i++)
            t[ty + i * 8][tx] = __ldg(W + (size_t)(by * 32 + ty + i * 8) * COUT + bx * 32 + tx);
        __syncthreads();
#pragma unroll
        for (int i = 0; i < 4; i++) {
            int nn = bx * 32 + ty + i * 8;
            int kk = by * 32 + tx;
            g_wc[(size_t)z * COUT * CIN + (size_t)nn * CIN + kk] = __float2half_rn(t[tx][ty + i * 8]);
        }
    } else {
        int idx = blk - CVT_X_BLKS - CVT_WC_BLKS;
        int bx = idx & 127, by = idx >> 7;
        int tx = threadIdx.x & 31, ty = threadIdx.x >> 5;
#pragma unroll
        for (int i = 0; i < 4; i++)
            t[ty + i * 8][tx] = __ldg(Wf + (size_t)(by * 32 + ty + i * 8) * OUTF + bx * 32 + tx);
        __syncthreads();
#pragma unroll
        for (int i = 0; i < 4; i++) {
            int nn = bx * 32 + ty + i * 8;
            int kk = by * 32 + tx;
            g_wf[(size_t)nn * HID + kk] = __float2half_rn(t[tx][ty + i * 8]);
        }
    }
}

// ---------------- shared PTX helpers ----------------
__device__ __forceinline__ uint32_t smem_u32(const void* p) {
    uint32_t a;
    asm("{ .reg .u64 t; cvta.to.shared.u64 t, %1; cvt.u32.u64 %0, t; }" : "=r"(a) : "l"(p));
    return a;
}
__device__ __forceinline__ void cp16(uint32_t sa, const void* ga) {
    asm volatile("cp.async.cg.shared.global [%0], [%1], 16;" :: "r"(sa), "l"(ga) : "memory");
}
__device__ __forceinline__ void ldm4(uint32_t* d, uint32_t a) {
    asm volatile("ldmatrix.sync.aligned.m8n8.x4.shared.b16 {%0,%1,%2,%3}, [%4];"
                 : "=r"(d[0]), "=r"(d[1]), "=r"(d[2]), "=r"(d[3]) : "r"(a));
}
__device__ __forceinline__ void mma16816(float* c, const uint32_t* a, uint32_t b0, uint32_t b1) {
    asm volatile(
        "mma.sync.aligned.m16n8k16.row.col.f32.f16.f16.f32 "
        "{%0,%1,%2,%3}, {%4,%5,%6,%7}, {%8,%9}, {%0,%1,%2,%3};"
        : "+f"(c[0]), "+f"(c[1]), "+f"(c[2]), "+f"(c[3])
        : "r"(a[0]), "r"(a[1]), "r"(a[2]), "r"(a[3]), "r"(b0), "r"(b1));
}

// ================= GEMM1: CTA 128x128, BK=32, warp tile 64x32 =================
#define STAGE_BYTES 24576
#define NSTAGES_BUF 4
#define SMEM_BYTES (NSTAGES_BUF * STAGE_BYTES)
#define OFF_AH 0
#define OFF_AL 8192
#define OFF_B  16384

__device__ __forceinline__ void prefetch_stage(
    uint32_t sbase,
    const uint4* __restrict__ Ah, const uint4* __restrict__ Al,
    const uint4* __restrict__ B,
    int ldv, int k0v)
{
    const int tid = threadIdx.x;
#pragma unroll
    for (int i = 0; i < 2; i++) {
        int c = tid + i * 256;
        int row = c >> 2, ch = c & 3;
        uint32_t so = (uint32_t)(row * 64 + ((ch ^ ((row >> 1) & 3)) << 4));
        size_t go = (size_t)row * ldv + k0v + ch;
        cp16(sbase + OFF_AH + so, Ah + go);
        cp16(sbase + OFF_AL + so, Al + go);
        cp16(sbase + OFF_B  + so, B  + go);
    }
    asm volatile("cp.async.commit_group;" ::: "memory");
}

__device__ __forceinline__ void mma_mainloop(
    const uint4* __restrict__ Ah, const uint4* __restrict__ Al,
    const uint4* __restrict__ B,
    int ldv, int nStages, uint32_t smb, float acc[4][4][4])
{
    const int lane = threadIdx.x & 31;
    const int wid  = threadIdx.x >> 5;
    const int warp_m = wid & 1;
    const int warp_n = wid >> 1;
    const int r8 = lane & 7;

    const int aro = ((lane >> 3) & 1) * 8 + r8;
    const int acs = lane >> 4;
    const int bro = (lane >> 4) * 8 + r8;
    const int bcs = (lane >> 3) & 1;

    int arow[4], aswz[4];
#pragma unroll
    for (int mt = 0; mt < 4; mt++) {
        arow[mt] = warp_m * 64 + mt * 16 + aro;
        aswz[mt] = (arow[mt] >> 1) & 3;
    }
    int brow[2], bswz[2];
#pragma unroll
    for (int np = 0; np < 2; np++) {
        brow[np] = warp_n * 32 + np * 16 + bro;
        bswz[np] = (brow[np] >> 1) & 3;
    }

    prefetch_stage(smb + 0 * STAGE_BYTES, Ah, Al, B, ldv, 0);
    prefetch_stage(smb + 1 * STAGE_BYTES, Ah, Al, B, ldv, 4);
    prefetch_stage(smb + 2 * STAGE_BYTES, Ah, Al, B, ldv, 8);

    for (int s = 0; s < nStages; s++) {
        asm volatile("cp.async.wait_group 2;" ::: "memory");
        __syncthreads();

        if (s + 3 < nStages)
            prefetch_stage(smb + ((s + 3) % NSTAGES_BUF) * STAGE_BYTES,
                           Ah, Al, B, ldv, (s + 3) * 4);
        else
            asm volatile("cp.async.commit_group;" ::: "memory");

        uint32_t st = smb + (s % NSTAGES_BUF) * STAGE_BYTES;

        uint32_t bfr[2][4];
        uint32_t ab[2][8];

#pragma unroll
        for (int np = 0; np < 2; np++) {
            uint32_t bo = (uint32_t)(brow[np] * 64 + ((bcs ^ bswz[np]) << 4));
            ldm4(bfr[np], st + OFF_B + bo);
        }
        {
            uint32_t ao = (uint32_t)(arow[0] * 64 + ((acs ^ aswz[0]) << 4));
            ldm4(&ab[0][0], st + OFF_AH + ao);
            ldm4(&ab[0][4], st + OFF_AL + ao);
        }

#pragma unroll
        for (int i = 0; i < 8; i++) {
            const int cur = i & 1;
            if (i == 4) {
#pragma unroll
                for (int np = 0; np < 2; np++) {
                    uint32_t bo = (uint32_t)(brow[np] * 64 + (((2 + bcs) ^ bswz[np]) << 4));
                    ldm4(bfr[np], st + OFF_B + bo);
                }
            }
            if (i < 7) {
                const int ni = i + 1;
                const int nks = ni >> 2, nmt = ni & 3;
                uint32_t ao = (uint32_t)(arow[nmt] * 64 + (((nks * 2 + acs) ^ aswz[nmt]) << 4));
                ldm4(&ab[ni & 1][0], st + OFF_AH + ao);
                ldm4(&ab[ni & 1][4], st + OFF_AL + ao);
            }
            const int mt = i & 3;
            const uint32_t* ah = &ab[cur][0];
            const uint32_t* al = &ab[cur][4];
#pragma unroll
            for (int nt = 0; nt < 4; nt++)
                mma16816(acc[mt][nt], ah, bfr[nt >> 1][(nt & 1) * 2], bfr[nt >> 1][(nt & 1) * 2 + 1]);
#pragma unroll
            for (int nt = 0; nt < 4; nt++)
                mma16816(acc[mt][nt], al, bfr[nt >> 1][(nt & 1) * 2], bfr[nt >> 1][(nt & 1) * 2 + 1]);
        }
    }
}

// GEMM1: h[:, z*512 + bx*128 ..] = x_sel[z] @ Wc[z]^T + bc ; emits fp16 hi/lo
__global__ __launch_bounds__(256, 2) void gemm1_kernel(const float* __restrict__ bc) {
    extern __shared__ char sm[];
    uint32_t smb = smem_u32(sm);
    const int bx = blockIdx.x, by = blockIdx.y, z = blockIdx.z;
    const int chunk = g_topk[z];

    const uint4* Ah = (const uint4*)(g_xh + (size_t)z * BSZ * CIN + (size_t)by * 128 * CIN);
    const uint4* Al = (const uint4*)(g_xl + (size_t)z * BSZ * CIN + (size_t)by * 128 * CIN);
    const uint4* B  = (const uint4*)(g_wc + (size_t)z * COUT * CIN + (size_t)bx * 128 * CIN);

    float acc[4][4][4];
#pragma unroll
    for (int a = 0; a < 4; a++)
#pragma unroll
        for (int b = 0; b < 4; b++)
#pragma unroll
            for (int c = 0; c < 4; c++) acc[a][b][c] = 0.0f;

    mma_mainloop(Ah, Al, B, CIN / 8, CIN / 32, smb, acc);

    const int lane = threadIdx.x & 31, wid = threadIdx.x >> 5;
    const int warp_m = wid & 1, warp_n = wid >> 1;
    const int g = lane >> 2, tg = lane & 3;
#pragma unroll
    for (int mt = 0; mt < 4; mt++) {
#pragma unroll
        for (int nt = 0; nt < 4; nt++) {
            int cl = warp_n * 32 + nt * 8 + tg * 2;
            int colg = z * COUT + bx * 128 + cl;
            float b0 = __ldg(bc + (size_t)chunk * COUT + bx * 128 + cl);
            float b1 = __ldg(bc + (size_t)chunk * COUT + bx * 128 + cl + 1);
#pragma unroll
            for (int half = 0; half < 2; half++) {
                int row = by * 128 + warp_m * 64 + mt * 16 + g + half * 8;
                float v0 = acc[mt][nt][half * 2 + 0] + b0;
                float v1 = acc[mt][nt][half * 2 + 1] + b1;
                __half h0, l0, h1, l1;
                split2h(v0, h0, l0); split2h(v1, h1, l1);
                size_t o = (size_t)row * HID + colg;
                *(ushort2*)(g_hh + o) = make_ushort2(__half_as_ushort(h0), __half_as_ushort(h1));
                *(ushort2*)(g_hl + o) = make_ushort2(__half_as_ushort(l0), __half_as_ushort(l1));
            }
        }
    }
}

// ================= GEMM2: CTA 128x64, BK=32, warp tile 32x32 =================
// 2048 tiles -> 6.92 waves on 296 slots (last wave 92% full).
// Stage: Ah 8K + Al 8K + B 4K = 20KB; 4 stages x 2 CTA = 160KB/SM.
#define STAGE2_BYTES 20480
#define NSTAGES2_BUF 4
#define SMEM2_BYTES (NSTAGES2_BUF * STAGE2_BYTES)
#define OFF2_AH 0
#define OFF2_AL 8192
#define OFF2_B  16384

__device__ __forceinline__ void prefetch_stage2(
    uint32_t sbase,
    const uint4* __restrict__ Ah, const uint4* __restrict__ Al,
    const uint4* __restrict__ B,
    int ldv, int k0v)
{
    const int tid = threadIdx.x;
    // 1280 cp16 total: [0,512) Ah, [512,1024) Al, [1024,1280) B
#pragma unroll
    for (int i = 0; i < 5; i++) {
        int c = tid + i * 256;
        if (c < 512) {
            int row = c >> 2, ch = c & 3;
            uint32_t so = (uint32_t)(row * 64 + ((ch ^ ((row >> 1) & 3)) << 4));
            cp16(sbase + OFF2_AH + so, Ah + (size_t)row * ldv + k0v + ch);
        } else if (c < 1024) {
            int cc = c - 512;
            int row = cc >> 2, ch = cc & 3;
            uint32_t so = (uint32_t)(row * 64 + ((ch ^ ((row >> 1) & 3)) << 4));
            cp16(sbase + OFF2_AL + so, Al + (size_t)row * ldv + k0v + ch);
        } else {
            int cc = c - 1024;
            int row = cc >> 2, ch = cc & 3;
            uint32_t so = (uint32_t)(row * 64 + ((ch ^ ((row >> 1) & 3)) << 4));
            cp16(sbase + OFF2_B + so, B + (size_t)row * ldv + k0v + ch);
        }
    }
    asm volatile("cp.async.commit_group;" ::: "memory");
}

__global__ __launch_bounds__(256, 2) void gemm2_kernel(const float* __restrict__ bf,
                                                       float* __restrict__ out) {
    extern __shared__ char sm[];
    uint32_t smb = smem_u32(sm);
    const int bx = blockIdx.x, by = blockIdx.y;   // bx: N tile (64), by: M tile (128)

    const uint4* Ah = (const uint4*)(g_hh + (size_t)by * 128 * HID);
    const uint4* Al = (const uint4*)(g_hl + (size_t)by * 128 * HID);
    const uint4* B  = (const uint4*)(g_wf + (size_t)bx * 64 * HID);

    const int lane = threadIdx.x & 31;
    const int wid  = threadIdx.x >> 5;
    const int warp_m = wid & 3;        // 4 m-groups of 32 rows
    const int warp_n = wid >> 2;       // 2 n-groups of 32 cols
    const int r8 = lane & 7;

    const int aro = ((lane >> 3) & 1) * 8 + r8;
    const int acs = lane >> 4;
    const int bro = (lane >> 4) * 8 + r8;
    const int bcs = (lane >> 3) & 1;

    int arow[2], aswz[2];
#pragma unroll
    for (int mt = 0; mt < 2; mt++) {
        arow[mt] = warp_m * 32 + mt * 16 + aro;
        aswz[mt] = (arow[mt] >> 1) & 3;
    }
    int brow[2], bswz[2];
#pragma unroll
    for (int np = 0; np < 2; np++) {
        brow[np] = warp_n * 32 + np * 16 + bro;
        bswz[np] = (brow[np] >> 1) & 3;
    }

    float acc[2][4][4];
#pragma unroll
    for (int a = 0; a < 2; a++)
#pragma unroll
        for (int b = 0; b < 4; b++)
#pragma unroll
            for (int c = 0; c < 4; c++) acc[a][b][c] = 0.0f;

    const int ldv = HID / 8;
    const int nStages = HID / 32;   // 32

    prefetch_stage2(smb + 0 * STAGE2_BYTES, Ah, Al, B, ldv, 0);
    prefetch_stage2(smb + 1 * STAGE2_BYTES, Ah, Al, B, ldv, 4);
    prefetch_stage2(smb + 2 * STAGE2_BYTES, Ah, Al, B, ldv, 8);

    for (int s = 0; s < nStages; s++) {
        asm volatile("cp.async.wait_group 2;" ::: "memory");
        __syncthreads();

        if (s + 3 < nStages)
            prefetch_stage2(smb + ((s + 3) % NSTAGES2_BUF) * STAGE2_BYTES,
                            Ah, Al, B, ldv, (s + 3) * 4);
        else
            asm volatile("cp.async.commit_group;" ::: "memory");

        uint32_t st = smb + (s % NSTAGES2_BUF) * STAGE2_BYTES;

        // B fragments for both k-steps up front (16 regs)
        uint32_t bfr[2][2][4];   // [ks][np][4]
#pragma unroll
        for (int ks = 0; ks < 2; ks++)
#pragma unroll
            for (int np = 0; np < 2; np++) {
                uint32_t bo = (uint32_t)(brow[np] * 64 + (((ks * 2 + bcs) ^ bswz[np]) << 4));
                ldm4(bfr[ks][np], st + OFF2_B + bo);
            }

        uint32_t ab[2][8];
        {
            uint32_t ao = (uint32_t)(arow[0] * 64 + ((acs ^ aswz[0]) << 4));
            ldm4(&ab[0][0], st + OFF2_AH + ao);
            ldm4(&ab[0][4], st + OFF2_AL + ao);
        }

        // 4 steps: i -> ks = i>>1, mt = i&1
#pragma unroll
        for (int i = 0; i < 4; i++) {
            const int cur = i & 1;
            if (i < 3) {
                const int ni = i + 1;
                const int nks = ni >> 1, nmt = ni & 1;
                uint32_t ao = (uint32_t)(arow[nmt] * 64 + (((nks * 2 + acs) ^ aswz[nmt]) << 4));
                ldm4(&ab[ni & 1][0], st + OFF2_AH + ao);
                ldm4(&ab[ni & 1][4], st + OFF2_AL + ao);
            }
            const int ks = i >> 1, mt = i & 1;
            const uint32_t* ah = &ab[cur][0];
            const uint32_t* al = &ab[cur][4];
#pragma unroll
            for (int nt = 0; nt < 4; nt++)
                mma16816(acc[mt][nt], ah, bfr[ks][nt >> 1][(nt & 1) * 2], bfr[ks][nt >> 1][(nt & 1) * 2 + 1]);
#pragma unroll
            for (int nt = 0; nt < 4; nt++)
                mma16816(acc[mt][nt], al, bfr[ks][nt >> 1][(nt & 1) * 2], bfr[ks][nt >> 1][(nt & 1) * 2 + 1]);
        }
    }

    const int g = lane >> 2, tg = lane & 3;
#pragma unroll
    for (int mt = 0; mt < 2; mt++) {
#pragma unroll
        for (int nt = 0; nt < 4; nt++) {
            int col = bx * 64 + warp_n * 32 + nt * 8 + tg * 2;
            float b0 = __ldg(bf + col);
            float b1 = __ldg(bf + col + 1);
#pragma unroll
            for (int half = 0; half < 2; half++) {
                int row = by * 128 + warp_m * 32 + mt * 16 + g + half * 8;
                float2 v;
                v.x = acc[mt][nt][half * 2 + 0] + b0;
                v.y = acc[mt][nt][half * 2 + 1] + b1;
                *(float2*)(out + (size_t)row * OUTF + col) = v;
            }
        }
    }
}

// ---------------- launcher ----------------
extern "C" void kernel_launch(void* const* d_in, const int* in_sizes, int n_in,
                              void* d_out, int out_size)
{
    const float* x  = (const float*)d_in[0];
    const float* Wc = (const float*)d_in[1];
    const float* bc = (const float*)d_in[2];
    const float* Wf = (const float*)d_in[3];
    const float* bf = (const float*)d_in[4];
    float* out = (float*)d_out;

    cudaFuncSetAttribute(gemm1_kernel, cudaFuncAttributeMaxDynamicSharedMemorySize, SMEM_BYTES);
    cudaFuncSetAttribute(gemm2_kernel, cudaFuncAttributeMaxDynamicSharedMemorySize, SMEM2_BYTES);

    activity_kernel<<<2048, 256>>>(x);                 // 1
    topk_kernel<<<1, 1>>>();                           // 2
    convert_all_kernel<<<CVT_TOTAL, 256>>>(x, Wc, Wf); // 3
    gemm1_kernel<<<dim3(4, 32, 2), 256, SMEM_BYTES>>>(bc);         // 4 (profiled)
    gemm2_kernel<<<dim3(64, 32), 256, SMEM2_BYTES>>>(bf, out);     // 5
}

// round 14
// speedup vs baseline: 1.1050x; 1.1050x over previous
#include <cuda_runtime.h>
#include <cuda_bf16.h>
#include <cuda_fp16.h>
#include <cstdint>

#define NCH   8
#define TOPK  2
#define BSZ   4096
#define INF   4096
#define CIN   512
#define COUT  512
#define HID   1024
#define OUTF  4096

// ---------------- device scratch (no allocations allowed) ----------------
__device__ float    g_act[NCH];       // zeroed at load; last activity block re-zeros
__device__ int      g_topk[TOPK];
__device__ unsigned g_adone = 0;

__device__ __half g_xh[(size_t)TOPK * BSZ * CIN];     // x selected, fp16 hi
__device__ __half g_xl[(size_t)TOPK * BSZ * CIN];     // x selected, fp16 lo
__device__ __half g_wc[(size_t)TOPK * COUT * CIN];    // W_chunk^T fp16 [N][K]
__device__ __half g_hh[(size_t)BSZ * HID];            // h fp16 hi
__device__ __half g_hl[(size_t)BSZ * HID];            // h fp16 lo
__device__ __half g_wf[(size_t)OUTF * HID];           // W_final^T fp16 [N][K]

// ---------------- routing (activity + fused topk) ----------------
__global__ void activity_kernel(const float* __restrict__ x) {
    float local[NCH];
#pragma unroll
    for (int c = 0; c < NCH; c++) local[c] = 0.0f;
    const long long total = (long long)BSZ * INF;
    const long long stride = (long long)gridDim.x * blockDim.x * 4;
    for (long long i = ((long long)blockIdx.x * blockDim.x + threadIdx.x) * 4; i < total; i += stride) {
        float4 v = *reinterpret_cast<const float4*>(x + i);
        int c = (int)((i >> 9) & 7);
        local[c] += fabsf(v.x) + fabsf(v.y) + fabsf(v.z) + fabsf(v.w);
    }
    __shared__ float sred[NCH];
    if (threadIdx.x < NCH) sred[threadIdx.x] = 0.0f;
    __syncthreads();
#pragma unroll
    for (int c = 0; c < NCH; c++) {
        float v = local[c];
#pragma unroll
        for (int off = 16; off > 0; off >>= 1) v += __shfl_xor_sync(0xffffffffu, v, off);
        if ((threadIdx.x & 31) == 0) atomicAdd(&sred[c], v);
    }
    __syncthreads();
    if (threadIdx.x < NCH) atomicAdd(&g_act[threadIdx.x], sred[threadIdx.x]);

    // last block computes top-2 (fused topk)
    __threadfence();
    __shared__ unsigned slast;
    if (threadIdx.x == 0) slast = atomicAdd(&g_adone, 1u);
    __syncthreads();
    if (slast == gridDim.x - 1 && threadIdx.x == 0) {
        float a[NCH];
#pragma unroll
        for (int i = 0; i < NCH; i++) a[i] = g_act[i];
        int best = 0;
#pragma unroll
        for (int i = 1; i < NCH; i++)
            if (a[i] > a[best]) best = i;
        int second = (best == 0) ? 1 : 0;
#pragma unroll
        for (int i = 0; i < NCH; i++)
            if (i != best && a[i] > a[second]) second = i;
        g_topk[0] = best;
        g_topk[1] = second;
#pragma unroll
        for (int i = 0; i < NCH; i++) g_act[i] = 0.0f;
        g_adone = 0;
    }
}

// ---------------- conversions ----------------
__device__ __forceinline__ void split2h(float v, __half& h, __half& l) {
    h = __float2half_rn(v);
    l = __float2half_rn(v - __half2float(h));
}

#define CVT_X_BLKS  4096
#define CVT_WC_BLKS 512
#define CVT_WF_BLKS 4096
#define CVT_TOTAL   (CVT_X_BLKS + CVT_WC_BLKS + CVT_WF_BLKS)

__global__ __launch_bounds__(256) void convert_all_kernel(
    const float* __restrict__ x,
    const float* __restrict__ Wc,
    const float* __restrict__ Wf)
{
    __shared__ float t[32][33];
    const int blk = blockIdx.x;

    if (blk < CVT_X_BLKS) {
        size_t g = (size_t)blk * 256 + threadIdx.x;
        int z = (int)(g >> 19);
        size_t r = g & 524287;
        int row = (int)(r >> 7);
        int c4  = (int)(r & 127);
        int chunk = g_topk[z];
        float4 v = __ldg((const float4*)(x + (size_t)row * INF + (size_t)chunk * CIN) + c4);
        __half h0, h1, h2, h3, l0, l1, l2, l3;
        split2h(v.x, h0, l0); split2h(v.y, h1, l1); split2h(v.z, h2, l2); split2h(v.w, h3, l3);
        size_t o = (size_t)z * BSZ * CIN + (size_t)row * CIN + (size_t)c4 * 4;
        *(ushort4*)(g_xh + o) = make_ushort4(__half_as_ushort(h0), __half_as_ushort(h1),
                                             __half_as_ushort(h2), __half_as_ushort(h3));
        *(ushort4*)(g_xl + o) = make_ushort4(__half_as_ushort(l0), __half_as_ushort(l1),
                                             __half_as_ushort(l2), __half_as_ushort(l3));
    } else if (blk < CVT_X_BLKS + CVT_WC_BLKS) {
        int idx = blk - CVT_X_BLKS;
        int z = idx >> 8, rem = idx & 255;
        int bx = rem & 15, by = rem >> 4;
        int tx = threadIdx.x & 31, ty = threadIdx.x >> 5;
        int chunk = g_topk[z];
        const float* W = Wc + (size_t)chunk * CIN * COUT;
#pragma unroll
        for (int i = 0; i < 4; i++)
            t[ty + i * 8][tx] = __ldg(W + (size_t)(by * 32 + ty + i * 8) * COUT + bx * 32 + tx);
        __syncthreads();
#pragma unroll
        for (int i = 0; i < 4; i++) {
            int nn = bx * 32 + ty + i * 8;
            int kk = by * 32 + tx;
            g_wc[(size_t)z * COUT * CIN + (size_t)nn * CIN + kk] = __float2half_rn(t[tx][ty + i * 8]);
        }
    } else {
        int idx = blk - CVT_X_BLKS - CVT_WC_BLKS;
        int bx = idx & 127, by = idx >> 7;
        int tx = threadIdx.x & 31, ty = threadIdx.x >> 5;
#pragma unroll
        for (int i = 0; i < 4; i++)
            t[ty + i * 8][tx] = __ldg(Wf + (size_t)(by * 32 + ty + i * 8) * OUTF + bx * 32 + tx);
        __syncthreads();
#pragma unroll
        for (int i = 0; i < 4; i++) {
            int nn = bx * 32 + ty + i * 8;
            int kk = by * 32 + tx;
            g_wf[(size_t)nn * HID + kk] = __float2half_rn(t[tx][ty + i * 8]);
        }
    }
}

// ---------------- shared PTX helpers ----------------
__device__ __forceinline__ uint32_t smem_u32(const void* p) {
    uint32_t a;
    asm("{ .reg .u64 t; cvta.to.shared.u64 t, %1; cvt.u32.u64 %0, t; }" : "=r"(a) : "l"(p));
    return a;
}
__device__ __forceinline__ void cp16(uint32_t sa, const void* ga) {
    asm volatile("cp.async.cg.shared.global [%0], [%1], 16;" :: "r"(sa), "l"(ga) : "memory");
}
__device__ __forceinline__ void ldm4(uint32_t* d, uint32_t a) {
    asm volatile("ldmatrix.sync.aligned.m8n8.x4.shared.b16 {%0,%1,%2,%3}, [%4];"
                 : "=r"(d[0]), "=r"(d[1]), "=r"(d[2]), "=r"(d[3]) : "r"(a));
}
__device__ __forceinline__ void mma16816(float* c, const uint32_t* a, uint32_t b0, uint32_t b1) {
    asm volatile(
        "mma.sync.aligned.m16n8k16.row.col.f32.f16.f16.f32 "
        "{%0,%1,%2,%3}, {%4,%5,%6,%7}, {%8,%9}, {%0,%1,%2,%3};"
        : "+f"(c[0]), "+f"(c[1]), "+f"(c[2]), "+f"(c[3])
        : "r"(a[0]), "r"(a[1]), "r"(a[2]), "r"(a[3]), "r"(b0), "r"(b1));
}

// ============ GEMM mainloop: CTA 128x128, BK=32, warp tile 32x64 ============
// warps 4 (M) x 2 (N). Per k-step per warp: A 2KB + B 2KB for 32 MMAs = 128B/MMA.
#define STAGE_BYTES 24576
#define NSTAGES_BUF 4
#define SMEM_BYTES (NSTAGES_BUF * STAGE_BYTES)
#define OFF_AH 0
#define OFF_AL 8192
#define OFF_B  16384

__device__ __forceinline__ void prefetch_stage(
    uint32_t sbase,
    const uint4* __restrict__ Ah, const uint4* __restrict__ Al,
    const uint4* __restrict__ B,
    int ldv, int k0v)
{
    const int tid = threadIdx.x;
#pragma unroll
    for (int i = 0; i < 2; i++) {
        int c = tid + i * 256;
        int row = c >> 2, ch = c & 3;
        uint32_t so = (uint32_t)(row * 64 + ((ch ^ ((row >> 1) & 3)) << 4));
        size_t go = (size_t)row * ldv + k0v + ch;
        cp16(sbase + OFF_AH + so, Ah + go);
        cp16(sbase + OFF_AL + so, Al + go);
        cp16(sbase + OFF_B  + so, B  + go);
    }
    asm volatile("cp.async.commit_group;" ::: "memory");
}

// acc[2][8][4]: mt in {0,1} (16-row tiles), nt in {0..7} (8-col tiles)
__device__ __forceinline__ void mma_mainloop(
    const uint4* __restrict__ Ah, const uint4* __restrict__ Al,
    const uint4* __restrict__ B,
    int ldv, int nStages, uint32_t smb, float acc[2][8][4])
{
    const int lane = threadIdx.x & 31;
    const int wid  = threadIdx.x >> 5;
    const int warp_m = wid & 3;        // 4 m-groups of 32 rows
    const int warp_n = wid >> 2;       // 2 n-groups of 64 cols
    const int r8 = lane & 7;

    const int aro = ((lane >> 3) & 1) * 8 + r8;   // A: row within m16
    const int acs = lane >> 4;                    // A: chunk select
    const int bro = (lane >> 4) * 8 + r8;         // B: row within n16
    const int bcs = (lane >> 3) & 1;              // B: chunk select

    int arow[2], aswz[2];
#pragma unroll
    for (int mt = 0; mt < 2; mt++) {
        arow[mt] = warp_m * 32 + mt * 16 + aro;
        aswz[mt] = (arow[mt] >> 1) & 3;
    }
    int brow[4], bswz[4];
#pragma unroll
    for (int np = 0; np < 4; np++) {
        brow[np] = warp_n * 64 + np * 16 + bro;
        bswz[np] = (brow[np] >> 1) & 3;
    }

    prefetch_stage(smb + 0 * STAGE_BYTES, Ah, Al, B, ldv, 0);
    prefetch_stage(smb + 1 * STAGE_BYTES, Ah, Al, B, ldv, 4);
    prefetch_stage(smb + 2 * STAGE_BYTES, Ah, Al, B, ldv, 8);

    for (int s = 0; s < nStages; s++) {
        asm volatile("cp.async.wait_group 2;" ::: "memory");
        __syncthreads();

        if (s + 3 < nStages)
            prefetch_stage(smb + ((s + 3) % NSTAGES_BUF) * STAGE_BYTES,
                           Ah, Al, B, ldv, (s + 3) * 4);
        else
            asm volatile("cp.async.commit_group;" ::: "memory");

        uint32_t st = smb + (s % NSTAGES_BUF) * STAGE_BYTES;

        uint32_t bfr[4][4];   // B frags for current ks (4 n16-tiles)
        uint32_t ab[2][8];    // double-buffered A (ah[4], al[4])

        // B frags for ks=0
#pragma unroll
        for (int np = 0; np < 4; np++) {
            uint32_t bo = (uint32_t)(brow[np] * 64 + ((bcs ^ bswz[np]) << 4));
            ldm4(bfr[np], st + OFF_B + bo);
        }
        // A frag for step 0 (ks=0, mt=0)
        {
            uint32_t ao = (uint32_t)(arow[0] * 64 + ((acs ^ aswz[0]) << 4));
            ldm4(&ab[0][0], st + OFF_AH + ao);
            ldm4(&ab[0][4], st + OFF_AL + ao);
        }

        // 4 steps: i -> ks = i>>1, mt = i&1 ; 16 MMAs per step
#pragma unroll
        for (int i = 0; i < 4; i++) {
            const int cur = i & 1;
            if (i == 2) {
                // B frags for ks=1
#pragma unroll
                for (int np = 0; np < 4; np++) {
                    uint32_t bo = (uint32_t)(brow[np] * 64 + (((2 + bcs) ^ bswz[np]) << 4));
                    ldm4(bfr[np], st + OFF_B + bo);
                }
            }
            if (i < 3) {
                const int ni = i + 1;
                const int nks = ni >> 1, nmt = ni & 1;
                uint32_t ao = (uint32_t)(arow[nmt] * 64 + (((nks * 2 + acs) ^ aswz[nmt]) << 4));
                ldm4(&ab[ni & 1][0], st + OFF_AH + ao);
                ldm4(&ab[ni & 1][4], st + OFF_AL + ao);
            }
            const int mt = i & 1;
            const uint32_t* ah = &ab[cur][0];
            const uint32_t* al = &ab[cur][4];
#pragma unroll
            for (int nt = 0; nt < 8; nt++)
                mma16816(acc[mt][nt], ah, bfr[nt >> 1][(nt & 1) * 2], bfr[nt >> 1][(nt & 1) * 2 + 1]);
#pragma unroll
            for (int nt = 0; nt < 8; nt++)
                mma16816(acc[mt][nt], al, bfr[nt >> 1][(nt & 1) * 2], bfr[nt >> 1][(nt & 1) * 2 + 1]);
        }
    }
}

// GEMM1: h[:, z*512 + bx*128 ..] = x_sel[z] @ Wc[z]^T + bc ; emits fp16 hi/lo
__global__ __launch_bounds__(256, 2) void gemm1_kernel(const float* __restrict__ bc) {
    extern __shared__ char sm[];
    uint32_t smb = smem_u32(sm);
    const int bx = blockIdx.x, by = blockIdx.y, z = blockIdx.z;
    const int chunk = g_topk[z];

    const uint4* Ah = (const uint4*)(g_xh + (size_t)z * BSZ * CIN + (size_t)by * 128 * CIN);
    const uint4* Al = (const uint4*)(g_xl + (size_t)z * BSZ * CIN + (size_t)by * 128 * CIN);
    const uint4* B  = (const uint4*)(g_wc + (size_t)z * COUT * CIN + (size_t)bx * 128 * CIN);

    float acc[2][8][4];
#pragma unroll
    for (int a = 0; a < 2; a++)
#pragma unroll
        for (int b = 0; b < 8; b++)
#pragma unroll
            for (int c = 0; c < 4; c++) acc[a][b][c] = 0.0f;

    mma_mainloop(Ah, Al, B, CIN / 8, CIN / 32, smb, acc);

    const int lane = threadIdx.x & 31, wid = threadIdx.x >> 5;
    const int warp_m = wid & 3, warp_n = wid >> 2;
    const int g = lane >> 2, tg = lane & 3;
#pragma unroll
    for (int mt = 0; mt < 2; mt++) {
#pragma unroll
        for (int nt = 0; nt < 8; nt++) {
            int cl = warp_n * 64 + nt * 8 + tg * 2;
            int colg = z * COUT + bx * 128 + cl;
            float b0 = __ldg(bc + (size_t)chunk * COUT + bx * 128 + cl);
            float b1 = __ldg(bc + (size_t)chunk * COUT + bx * 128 + cl + 1);
#pragma unroll
            for (int half = 0; half < 2; half++) {
                int row = by * 128 + warp_m * 32 + mt * 16 + g + half * 8;
                float v0 = acc[mt][nt][half * 2 + 0] + b0;
                float v1 = acc[mt][nt][half * 2 + 1] + b1;
                __half h0, l0, h1, l1;
                split2h(v0, h0, l0); split2h(v1, h1, l1);
                size_t o = (size_t)row * HID + colg;
                *(ushort2*)(g_hh + o) = make_ushort2(__half_as_ushort(h0), __half_as_ushort(h1));
                *(ushort2*)(g_hl + o) = make_ushort2(__half_as_ushort(l0), __half_as_ushort(l1));
            }
        }
    }
}

// GEMM2: out = h @ W_final + b_final (CTA 128x128, grid 32x32)
__global__ __launch_bounds__(256, 2) void gemm2_kernel(const float* __restrict__ bf,
                                                       float* __restrict__ out) {
    extern __shared__ char sm[];
    uint32_t smb = smem_u32(sm);
    const int bx = blockIdx.x, by = blockIdx.y;

    const uint4* Ah = (const uint4*)(g_hh + (size_t)by * 128 * HID);
    const uint4* Al = (const uint4*)(g_hl + (size_t)by * 128 * HID);
    const uint4* B  = (const uint4*)(g_wf + (size_t)bx * 128 * HID);

    float acc[2][8][4];
#pragma unroll
    for (int a = 0; a < 2; a++)
#pragma unroll
        for (int b = 0; b < 8; b++)
#pragma unroll
            for (int c = 0; c < 4; c++) acc[a][b][c] = 0.0f;

    mma_mainloop(Ah, Al, B, HID / 8, HID / 32, smb, acc);

    const int lane = threadIdx.x & 31, wid = threadIdx.x >> 5;
    const int warp_m = wid & 3, warp_n = wid >> 2;
    const int g = lane >> 2, tg = lane & 3;
#pragma unroll
    for (int mt = 0; mt < 2; mt++) {
#pragma unroll
        for (int nt = 0; nt < 8; nt++) {
            int col = bx * 128 + warp_n * 64 + nt * 8 + tg * 2;
            float b0 = __ldg(bf + col);
            float b1 = __ldg(bf + col + 1);
#pragma unroll
            for (int half = 0; half < 2; half++) {
                int row = by * 128 + warp_m * 32 + mt * 16 + g + half * 8;
                float2 v;
                v.x = acc[mt][nt][half * 2 + 0] + b0;
                v.y = acc[mt][nt][half * 2 + 1] + b1;
                *(float2*)(out + (size_t)row * OUTF + col) = v;
            }
        }
    }
}

// ---------------- launcher ----------------
extern "C" void kernel_launch(void* const* d_in, const int* in_sizes, int n_in,
                              void* d_out, int out_size)
{
    const float* x  = (const float*)d_in[0];
    const float* Wc = (const float*)d_in[1];
    const float* bc = (const float*)d_in[2];
    const float* Wf = (const float*)d_in[3];
    const float* bf = (const float*)d_in[4];
    float* out = (float*)d_out;

    cudaFuncSetAttribute(gemm1_kernel, cudaFuncAttributeMaxDynamicSharedMemorySize, SMEM_BYTES);
    cudaFuncSetAttribute(gemm2_kernel, cudaFuncAttributeMaxDynamicSharedMemorySize, SMEM_BYTES);

    activity_kernel<<<2048, 256>>>(x);                 // 1 (topk fused into last block)
    convert_all_kernel<<<CVT_TOTAL, 256>>>(x, Wc, Wf); // 2
    gemm1_kernel<<<dim3(4, 32, 2), 256, SMEM_BYTES>>>(bc);        // 3 (profiled at -s5? no: launch idx)
    gemm2_kernel<<<dim3(32, 32), 256, SMEM_BYTES>>>(bf, out);     // 4
}

// round 16
// speedup vs baseline: 1.1955x; 1.0819x over previous
#include <cuda_runtime.h>
#include <cuda_bf16.h>
#include <cuda_fp16.h>
#include <cstdint>

#define NCH   8
#define TOPK  2
#define BSZ   4096
#define INF   4096
#define CIN   512
#define COUT  512
#define HID   1024
#define OUTF  4096

// ---------------- device scratch (no allocations allowed) ----------------
__device__ float    g_act[NCH];       // zeroed at load; last activity block re-zeros
__device__ int      g_topk[TOPK];
__device__ unsigned g_adone = 0;

__device__ __half g_xh[(size_t)TOPK * BSZ * CIN];     // x selected, fp16 hi
__device__ __half g_xl[(size_t)TOPK * BSZ * CIN];     // x selected, fp16 lo
__device__ __half g_wc[(size_t)TOPK * COUT * CIN];    // W_chunk^T fp16 [N][K]
__device__ __half g_hh[(size_t)BSZ * HID];            // h fp16 hi
__device__ __half g_hl[(size_t)BSZ * HID];            // h fp16 lo
__device__ __half g_wf[(size_t)OUTF * HID];           // W_final^T fp16 [N][K]

// ---------------- routing (activity + fused topk) ----------------
__global__ void activity_kernel(const float* __restrict__ x) {
    float local[NCH];
#pragma unroll
    for (int c = 0; c < NCH; c++) local[c] = 0.0f;
    const long long total = (long long)BSZ * INF;
    const long long stride = (long long)gridDim.x * blockDim.x * 4;
    for (long long i = ((long long)blockIdx.x * blockDim.x + threadIdx.x) * 4; i < total; i += stride) {
        float4 v = *reinterpret_cast<const float4*>(x + i);
        int c = (int)((i >> 9) & 7);
        local[c] += fabsf(v.x) + fabsf(v.y) + fabsf(v.z) + fabsf(v.w);
    }
    __shared__ float sred[NCH];
    if (threadIdx.x < NCH) sred[threadIdx.x] = 0.0f;
    __syncthreads();
#pragma unroll
    for (int c = 0; c < NCH; c++) {
        float v = local[c];
#pragma unroll
        for (int off = 16; off > 0; off >>= 1) v += __shfl_xor_sync(0xffffffffu, v, off);
        if ((threadIdx.x & 31) == 0) atomicAdd(&sred[c], v);
    }
    __syncthreads();
    if (threadIdx.x < NCH) atomicAdd(&g_act[threadIdx.x], sred[threadIdx.x]);

    __threadfence();
    __shared__ unsigned slast;
    if (threadIdx.x == 0) slast = atomicAdd(&g_adone, 1u);
    __syncthreads();
    if (slast == gridDim.x - 1 && threadIdx.x == 0) {
        float a[NCH];
#pragma unroll
        for (int i = 0; i < NCH; i++) a[i] = g_act[i];
        int best = 0;
#pragma unroll
        for (int i = 1; i < NCH; i++)
            if (a[i] > a[best]) best = i;
        int second = (best == 0) ? 1 : 0;
#pragma unroll
        for (int i = 0; i < NCH; i++)
            if (i != best && a[i] > a[second]) second = i;
        g_topk[0] = best;
        g_topk[1] = second;
#pragma unroll
        for (int i = 0; i < NCH; i++) g_act[i] = 0.0f;
        g_adone = 0;
    }
}

// ---------------- conversions ----------------
__device__ __forceinline__ void split2h(float v, __half& h, __half& l) {
    h = __float2half_rn(v);
    l = __float2half_rn(v - __half2float(h));
}

#define CVT_X_BLKS  4096
#define CVT_WC_BLKS 512
#define CVT_WF_BLKS 4096
#define CVT_TOTAL   (CVT_X_BLKS + CVT_WC_BLKS + CVT_WF_BLKS)

__global__ __launch_bounds__(256) void convert_all_kernel(
    const float* __restrict__ x,
    const float* __restrict__ Wc,
    const float* __restrict__ Wf)
{
    __shared__ float t[32][33];
    const int blk = blockIdx.x;

    if (blk < CVT_X_BLKS) {
        size_t g = (size_t)blk * 256 + threadIdx.x;
        int z = (int)(g >> 19);
        size_t r = g & 524287;
        int row = (int)(r >> 7);
        int c4  = (int)(r & 127);
        int chunk = g_topk[z];
        float4 v = __ldg((const float4*)(x + (size_t)row * INF + (size_t)chunk * CIN) + c4);
        __half h0, h1, h2, h3, l0, l1, l2, l3;
        split2h(v.x, h0, l0); split2h(v.y, h1, l1); split2h(v.z, h2, l2); split2h(v.w, h3, l3);
        size_t o = (size_t)z * BSZ * CIN + (size_t)row * CIN + (size_t)c4 * 4;
        *(ushort4*)(g_xh + o) = make_ushort4(__half_as_ushort(h0), __half_as_ushort(h1),
                                             __half_as_ushort(h2), __half_as_ushort(h3));
        *(ushort4*)(g_xl + o) = make_ushort4(__half_as_ushort(l0), __half_as_ushort(l1),
                                             __half_as_ushort(l2), __half_as_ushort(l3));
    } else if (blk < CVT_X_BLKS + CVT_WC_BLKS) {
        int idx = blk - CVT_X_BLKS;
        int z = idx >> 8, rem = idx & 255;
        int bx = rem & 15, by = rem >> 4;
        int tx = threadIdx.x & 31, ty = threadIdx.x >> 5;
        int chunk = g_topk[z];
        const float* W = Wc + (size_t)chunk * CIN * COUT;
#pragma unroll
        for (int i = 0; i < 4; i++)
            t[ty + i * 8][tx] = __ldg(W + (size_t)(by * 32 + ty + i * 8) * COUT + bx * 32 + tx);
        __syncthreads();
#pragma unroll
        for (int i = 0; i < 4; i++) {
            int nn = bx * 32 + ty + i * 8;
            int kk = by * 32 + tx;
            g_wc[(size_t)z * COUT * CIN + (size_t)nn * CIN + kk] = __float2half_rn(t[tx][ty + i * 8]);
        }
    } else {
        int idx = blk - CVT_X_BLKS - CVT_WC_BLKS;
        int bx = idx & 127, by = idx >> 7;
        int tx = threadIdx.x & 31, ty = threadIdx.x >> 5;
#pragma unroll
        for (int i = 0; i < 4; i++)
            t[ty + i * 8][tx] = __ldg(Wf + (size_t)(by * 32 + ty + i * 8) * OUTF + bx * 32 + tx);
        __syncthreads();
#pragma unroll
        for (int i = 0; i < 4; i++) {
            int nn = bx * 32 + ty + i * 8;
            int kk = by * 32 + tx;
            g_wf[(size_t)nn * HID + kk] = __float2half_rn(t[tx][ty + i * 8]);
        }
    }
}

// ---------------- shared PTX helpers ----------------
__device__ __forceinline__ uint32_t smem_u32(const void* p) {
    uint32_t a;
    asm("{ .reg .u64 t; cvta.to.shared.u64 t, %1; cvt.u32.u64 %0, t; }" : "=r"(a) : "l"(p));
    return a;
}
__device__ __forceinline__ void cp16(uint32_t sa, const void* ga) {
    asm volatile("cp.async.cg.shared.global [%0], [%1], 16;" :: "r"(sa), "l"(ga) : "memory");
}
__device__ __forceinline__ void ldm4(uint32_t* d, uint32_t a) {
    asm volatile("ldmatrix.sync.aligned.m8n8.x4.shared.b16 {%0,%1,%2,%3}, [%4];"
                 : "=r"(d[0]), "=r"(d[1]), "=r"(d[2]), "=r"(d[3]) : "r"(a));
}
__device__ __forceinline__ void mma16816(float* c, const uint32_t* a, uint32_t b0, uint32_t b1) {
    asm volatile(
        "mma.sync.aligned.m16n8k16.row.col.f32.f16.f16.f32 "
        "{%0,%1,%2,%3}, {%4,%5,%6,%7}, {%8,%9}, {%0,%1,%2,%3};"
        : "+f"(c[0]), "+f"(c[1]), "+f"(c[2]), "+f"(c[3])
        : "r"(a[0]), "r"(a[1]), "r"(a[2]), "r"(a[3]), "r"(b0), "r"(b1));
}

// ============ GEMM mainloop: CTA 128x128, BK=64, warp tile 32x64 ============
// warps 4 (M) x 2 (N). Stage: Ah 16K + Al 16K + B 16K = 48KB; double-buffered
// (96KB/CTA, 2 CTAs/SM = 192KB). Row = 128B (8 chunks), SW128: phys ch = ch^(row&7).
#define STAGE_BYTES 49152
#define SMEM_BYTES (2 * STAGE_BYTES)
#define OFF_AH 0
#define OFF_AL 16384
#define OFF_B  32768

// ldv = K/8 (uint4 stride). k0v = stage*8 (64 halves = 8 uint4).
__device__ __forceinline__ void prefetch_stage(
    uint32_t sbase,
    const uint4* __restrict__ Ah, const uint4* __restrict__ Al,
    const uint4* __restrict__ B,
    int ldv, int k0v)
{
    const int tid = threadIdx.x;
#pragma unroll
    for (int i = 0; i < 4; i++) {
        int c = tid + i * 256;               // 0..1023
        int row = c >> 3, ch = c & 7;
        uint32_t so = (uint32_t)(row * 128 + ((ch ^ (row & 7)) << 4));
        size_t go = (size_t)row * ldv + k0v + ch;
        cp16(sbase + OFF_AH + so, Ah + go);
        cp16(sbase + OFF_AL + so, Al + go);
        cp16(sbase + OFF_B  + so, B  + go);
    }
    asm volatile("cp.async.commit_group;" ::: "memory");
}

// acc[2][8][4]: mt in {0,1} (16-row tiles), nt in {0..7} (8-col tiles)
__device__ __forceinline__ void mma_mainloop(
    const uint4* __restrict__ Ah, const uint4* __restrict__ Al,
    const uint4* __restrict__ B,
    int ldv, int nStages, uint32_t smb, float acc[2][8][4])
{
    const int lane = threadIdx.x & 31;
    const int wid  = threadIdx.x >> 5;
    const int warp_m = wid & 3;        // 4 m-groups of 32 rows
    const int warp_n = wid >> 2;       // 2 n-groups of 64 cols
    const int r8 = lane & 7;

    const int aro = ((lane >> 3) & 1) * 8 + r8;   // A: row within m16
    const int acs = lane >> 4;                    // A: chunk select (0/1)
    const int bro = (lane >> 4) * 8 + r8;         // B: row within n16
    const int bcs = (lane >> 3) & 1;              // B: chunk select (0/1)

    int arow[2], aswz[2];
#pragma unroll
    for (int mt = 0; mt < 2; mt++) {
        arow[mt] = warp_m * 32 + mt * 16 + aro;
        aswz[mt] = arow[mt] & 7;
    }
    int brow[4], bswz[4];
#pragma unroll
    for (int np = 0; np < 4; np++) {
        brow[np] = warp_n * 64 + np * 16 + bro;
        bswz[np] = brow[np] & 7;
    }

    prefetch_stage(smb, Ah, Al, B, ldv, 0);

    for (int s = 0; s < nStages; s++) {
        asm volatile("cp.async.wait_group 0;" ::: "memory");
        __syncthreads();

        if (s + 1 < nStages)
            prefetch_stage(smb + ((s + 1) & 1) * STAGE_BYTES, Ah, Al, B, ldv, (s + 1) * 8);

        uint32_t st = smb + (s & 1) * STAGE_BYTES;

        uint32_t bfr[4][4];   // B frags for current ks
        uint32_t ab[2][8];    // double-buffered A (ah[4], al[4])

        // B frags for ks=0
#pragma unroll
        for (int np = 0; np < 4; np++) {
            uint32_t bo = (uint32_t)(brow[np] * 128 + ((bcs ^ bswz[np]) << 4));
            ldm4(bfr[np], st + OFF_B + bo);
        }
        // A frag for step 0 (ks=0, mt=0)
        {
            uint32_t ao = (uint32_t)(arow[0] * 128 + ((acs ^ aswz[0]) << 4));
            ldm4(&ab[0][0], st + OFF_AH + ao);
            ldm4(&ab[0][4], st + OFF_AL + ao);
        }

        // 8 steps: i -> ks = i>>1 (k16-pair), mt = i&1 ; 16 MMAs per step
#pragma unroll
        for (int i = 0; i < 8; i++) {
            const int cur = i & 1;
            if (i && (i & 1) == 0) {
                const int ks = i >> 1;
#pragma unroll
                for (int np = 0; np < 4; np++) {
                    uint32_t bo = (uint32_t)(brow[np] * 128 + (((ks * 2 + bcs) ^ bswz[np]) << 4));
                    ldm4(bfr[np], st + OFF_B + bo);
                }
            }
            if (i < 7) {
                const int ni = i + 1;
                const int nks = ni >> 1, nmt = ni & 1;
                uint32_t ao = (uint32_t)(arow[nmt] * 128 + (((nks * 2 + acs) ^ aswz[nmt]) << 4));
                ldm4(&ab[ni & 1][0], st + OFF_AH + ao);
                ldm4(&ab[ni & 1][4], st + OFF_AL + ao);
            }
            const int mt = i & 1;
            const uint32_t* ah = &ab[cur][0];
            const uint32_t* al = &ab[cur][4];
#pragma unroll
            for (int nt = 0; nt < 8; nt++)
                mma16816(acc[mt][nt], ah, bfr[nt >> 1][(nt & 1) * 2], bfr[nt >> 1][(nt & 1) * 2 + 1]);
#pragma unroll
            for (int nt = 0; nt < 8; nt++)
                mma16816(acc[mt][nt], al, bfr[nt >> 1][(nt & 1) * 2], bfr[nt >> 1][(nt & 1) * 2 + 1]);
        }
    }
}

// GEMM1: h[:, z*512 + bx*128 ..] = x_sel[z] @ Wc[z]^T + bc ; emits fp16 hi/lo
__global__ __launch_bounds__(256, 2) void gemm1_kernel(const float* __restrict__ bc) {
    extern __shared__ char sm[];
    uint32_t smb = smem_u32(sm);
    const int bx = blockIdx.x, by = blockIdx.y, z = blockIdx.z;
    const int chunk = g_topk[z];

    const uint4* Ah = (const uint4*)(g_xh + (size_t)z * BSZ * CIN + (size_t)by * 128 * CIN);
    const uint4* Al = (const uint4*)(g_xl + (size_t)z * BSZ * CIN + (size_t)by * 128 * CIN);
    const uint4* B  = (const uint4*)(g_wc + (size_t)z * COUT * CIN + (size_t)bx * 128 * CIN);

    float acc[2][8][4];
#pragma unroll
    for (int a = 0; a < 2; a++)
#pragma unroll
        for (int b = 0; b < 8; b++)
#pragma unroll
            for (int c = 0; c < 4; c++) acc[a][b][c] = 0.0f;

    mma_mainloop(Ah, Al, B, CIN / 8, CIN / 64, smb, acc);

    const int lane = threadIdx.x & 31, wid = threadIdx.x >> 5;
    const int warp_m = wid & 3, warp_n = wid >> 2;
    const int g = lane >> 2, tg = lane & 3;
#pragma unroll
    for (int mt = 0; mt < 2; mt++) {
#pragma unroll
        for (int nt = 0; nt < 8; nt++) {
            int cl = warp_n * 64 + nt * 8 + tg * 2;
            int colg = z * COUT + bx * 128 + cl;
            float b0 = __ldg(bc + (size_t)chunk * COUT + bx * 128 + cl);
            float b1 = __ldg(bc + (size_t)chunk * COUT + bx * 128 + cl + 1);
#pragma unroll
            for (int half = 0; half < 2; half++) {
                int row = by * 128 + warp_m * 32 + mt * 16 + g + half * 8;
                float v0 = acc[mt][nt][half * 2 + 0] + b0;
                float v1 = acc[mt][nt][half * 2 + 1] + b1;
                __half h0, l0, h1, l1;
                split2h(v0, h0, l0); split2h(v1, h1, l1);
                size_t o = (size_t)row * HID + colg;
                *(ushort2*)(g_hh + o) = make_ushort2(__half_as_ushort(h0), __half_as_ushort(h1));
                *(ushort2*)(g_hl + o) = make_ushort2(__half_as_ushort(l0), __half_as_ushort(l1));
            }
        }
    }
}

// GEMM2: out = h @ W_final + b_final (CTA 128x128, grid 32x32)
__global__ __launch_bounds__(256, 2) void gemm2_kernel(const float* __restrict__ bf,
                                                       float* __restrict__ out) {
    extern __shared__ char sm[];
    uint32_t smb = smem_u32(sm);
    const int bx = blockIdx.x, by = blockIdx.y;

    const uint4* Ah = (const uint4*)(g_hh + (size_t)by * 128 * HID);
    const uint4* Al = (const uint4*)(g_hl + (size_t)by * 128 * HID);
    const uint4* B  = (const uint4*)(g_wf + (size_t)bx * 128 * HID);

    float acc[2][8][4];
#pragma unroll
    for (int a = 0; a < 2; a++)
#pragma unroll
        for (int b = 0; b < 8; b++)
#pragma unroll
            for (int c = 0; c < 4; c++) acc[a][b][c] = 0.0f;

    mma_mainloop(Ah, Al, B, HID / 8, HID / 64, smb, acc);

    const int lane = threadIdx.x & 31, wid = threadIdx.x >> 5;
    const int warp_m = wid & 3, warp_n = wid >> 2;
    const int g = lane >> 2, tg = lane & 3;
#pragma unroll
    for (int mt = 0; mt < 2; mt++) {
#pragma unroll
        for (int nt = 0; nt < 8; nt++) {
            int col = bx * 128 + warp_n * 64 + nt * 8 + tg * 2;
            float b0 = __ldg(bf + col);
            float b1 = __ldg(bf + col + 1);
#pragma unroll
            for (int half = 0; half < 2; half++) {
                int row = by * 128 + warp_m * 32 + mt * 16 + g + half * 8;
                float2 v;
                v.x = acc[mt][nt][half * 2 + 0] + b0;
                v.y = acc[mt][nt][half * 2 + 1] + b1;
                *(float2*)(out + (size_t)row * OUTF + col) = v;
            }
        }
    }
}

// ---------------- launcher ----------------
extern "C" void kernel_launch(void* const* d_in, const int* in_sizes, int n_in,
                              void* d_out, int out_size)
{
    const float* x  = (const float*)d_in[0];
    const float* Wc = (const float*)d_in[1];
    const float* bc = (const float*)d_in[2];
    const float* Wf = (const float*)d_in[3];
    const float* bf = (const float*)d_in[4];
    float* out = (float*)d_out;

    cudaFuncSetAttribute(gemm1_kernel, cudaFuncAttributeMaxDynamicSharedMemorySize, SMEM_BYTES);
    cudaFuncSetAttribute(gemm2_kernel, cudaFuncAttributeMaxDynamicSharedMemorySize, SMEM_BYTES);

    activity_kernel<<<2048, 256>>>(x);                 // 1 (topk fused)
    convert_all_kernel<<<CVT_TOTAL, 256>>>(x, Wc, Wf); // 2
    gemm1_kernel<<<dim3(4, 32, 2), 256, SMEM_BYTES>>>(bc);        // 3
    gemm2_kernel<<<dim3(32, 32), 256, SMEM_BYTES>>>(bf, out);     // 4
}

// round 17
// speedup vs baseline: 1.8121x; 1.5158x over previous
#include <cuda_runtime.h>
#include <cuda_bf16.h>
#include <cuda_fp16.h>
#include <cstdint>

#define NCH   8
#define TOPK  2
#define BSZ   4096
#define INF   4096
#define CIN   512
#define COUT  512
#define HID   1024
#define OUTF  4096

// ---------------- device scratch (no allocations allowed) ----------------
__device__ float    g_act[NCH];       // zeroed at load; last activity block re-zeros
__device__ int      g_topk[TOPK];
__device__ unsigned g_adone = 0;

__device__ __half g_x16[(size_t)TOPK * BSZ * CIN];    // x selected, fp16
__device__ __half g_wc[(size_t)TOPK * COUT * CIN];    // W_chunk^T fp16 [N][K]
__device__ __half g_h16[(size_t)BSZ * HID];           // h fp16
__device__ __half g_wf[(size_t)OUTF * HID];           // W_final^T fp16 [N][K]

// ---------------- routing (activity + fused topk) ----------------
__global__ void activity_kernel(const float* __restrict__ x) {
    float local[NCH];
#pragma unroll
    for (int c = 0; c < NCH; c++) local[c] = 0.0f;
    const long long total = (long long)BSZ * INF;
    const long long stride = (long long)gridDim.x * blockDim.x * 4;
    for (long long i = ((long long)blockIdx.x * blockDim.x + threadIdx.x) * 4; i < total; i += stride) {
        float4 v = *reinterpret_cast<const float4*>(x + i);
        int c = (int)((i >> 9) & 7);
        local[c] += fabsf(v.x) + fabsf(v.y) + fabsf(v.z) + fabsf(v.w);
    }
    __shared__ float sred[NCH];
    if (threadIdx.x < NCH) sred[threadIdx.x] = 0.0f;
    __syncthreads();
#pragma unroll
    for (int c = 0; c < NCH; c++) {
        float v = local[c];
#pragma unroll
        for (int off = 16; off > 0; off >>= 1) v += __shfl_xor_sync(0xffffffffu, v, off);
        if ((threadIdx.x & 31) == 0) atomicAdd(&sred[c], v);
    }
    __syncthreads();
    if (threadIdx.x < NCH) atomicAdd(&g_act[threadIdx.x], sred[threadIdx.x]);

    __threadfence();
    __shared__ unsigned slast;
    if (threadIdx.x == 0) slast = atomicAdd(&g_adone, 1u);
    __syncthreads();
    if (slast == gridDim.x - 1 && threadIdx.x == 0) {
        float a[NCH];
#pragma unroll
        for (int i = 0; i < NCH; i++) a[i] = g_act[i];
        int best = 0;
#pragma unroll
        for (int i = 1; i < NCH; i++)
            if (a[i] > a[best]) best = i;
        int second = (best == 0) ? 1 : 0;
#pragma unroll
        for (int i = 0; i < NCH; i++)
            if (i != best && a[i] > a[second]) second = i;
        g_topk[0] = best;
        g_topk[1] = second;
#pragma unroll
        for (int i = 0; i < NCH; i++) g_act[i] = 0.0f;
        g_adone = 0;
    }
}

// ---------------- conversions (all plain fp16) ----------------
#define CVT_X_BLKS  2048
#define CVT_WC_BLKS 512
#define CVT_WF_BLKS 4096
#define CVT_TOTAL   (CVT_X_BLKS + CVT_WC_BLKS + CVT_WF_BLKS)

__global__ __launch_bounds__(256) void convert_all_kernel(
    const float* __restrict__ x,
    const float* __restrict__ Wc,
    const float* __restrict__ Wf)
{
    __shared__ float t[32][33];
    const int blk = blockIdx.x;

    if (blk < CVT_X_BLKS) {
        // 2 * 4096 * 128 float4-groups / 256 threads = 4096 blocks worth at 1 group;
        // use 2 groups per thread -> 2048 blocks
        size_t base = (size_t)blk * 512 + threadIdx.x;
#pragma unroll
        for (int rep = 0; rep < 2; rep++) {
            size_t g = base + rep * 256;
            int z = (int)(g >> 19);
            size_t r = g & 524287;
            int row = (int)(r >> 7);
            int c4  = (int)(r & 127);
            int chunk = g_topk[z];
            float4 v = __ldg((const float4*)(x + (size_t)row * INF + (size_t)chunk * CIN) + c4);
            size_t o = (size_t)z * BSZ * CIN + (size_t)row * CIN + (size_t)c4 * 4;
            *(ushort4*)(g_x16 + o) = make_ushort4(
                __half_as_ushort(__float2half_rn(v.x)), __half_as_ushort(__float2half_rn(v.y)),
                __half_as_ushort(__float2half_rn(v.z)), __half_as_ushort(__float2half_rn(v.w)));
        }
    } else if (blk < CVT_X_BLKS + CVT_WC_BLKS) {
        int idx = blk - CVT_X_BLKS;
        int z = idx >> 8, rem = idx & 255;
        int bx = rem & 15, by = rem >> 4;
        int tx = threadIdx.x & 31, ty = threadIdx.x >> 5;
        int chunk = g_topk[z];
        const float* W = Wc + (size_t)chunk * CIN * COUT;
#pragma unroll
        for (int i = 0; i < 4; i++)
            t[ty + i * 8][tx] = __ldg(W + (size_t)(by * 32 + ty + i * 8) * COUT + bx * 32 + tx);
        __syncthreads();
#pragma unroll
        for (int i = 0; i < 4; i++) {
            int nn = bx * 32 + ty + i * 8;
            int kk = by * 32 + tx;
            g_wc[(size_t)z * COUT * CIN + (size_t)nn * CIN + kk] = __float2half_rn(t[tx][ty + i * 8]);
        }
    } else {
        int idx = blk - CVT_X_BLKS - CVT_WC_BLKS;
        int bx = idx & 127, by = idx >> 7;
        int tx = threadIdx.x & 31, ty = threadIdx.x >> 5;
#pragma unroll
        for (int i = 0; i < 4; i++)
            t[ty + i * 8][tx] = __ldg(Wf + (size_t)(by * 32 + ty + i * 8) * OUTF + bx * 32 + tx);
        __syncthreads();
#pragma unroll
        for (int i = 0; i < 4; i++) {
            int nn = bx * 32 + ty + i * 8;
            int kk = by * 32 + tx;
            g_wf[(size_t)nn * HID + kk] = __float2half_rn(t[tx][ty + i * 8]);
        }
    }
}

// ---------------- shared PTX helpers ----------------
__device__ __forceinline__ uint32_t smem_u32(const void* p) {
    uint32_t a;
    asm("{ .reg .u64 t; cvta.to.shared.u64 t, %1; cvt.u32.u64 %0, t; }" : "=r"(a) : "l"(p));
    return a;
}
__device__ __forceinline__ void cp16(uint32_t sa, const void* ga) {
    asm volatile("cp.async.cg.shared.global [%0], [%1], 16;" :: "r"(sa), "l"(ga) : "memory");
}
__device__ __forceinline__ void ldm4(uint32_t* d, uint32_t a) {
    asm volatile("ldmatrix.sync.aligned.m8n8.x4.shared.b16 {%0,%1,%2,%3}, [%4];"
                 : "=r"(d[0]), "=r"(d[1]), "=r"(d[2]), "=r"(d[3]) : "r"(a));
}
__device__ __forceinline__ void mma16816(float* c, const uint32_t* a, uint32_t b0, uint32_t b1) {
    asm volatile(
        "mma.sync.aligned.m16n8k16.row.col.f32.f16.f16.f32 "
        "{%0,%1,%2,%3}, {%4,%5,%6,%7}, {%8,%9}, {%0,%1,%2,%3};"
        : "+f"(c[0]), "+f"(c[1]), "+f"(c[2]), "+f"(c[3])
        : "r"(a[0]), "r"(a[1]), "r"(a[2]), "r"(a[3]), "r"(b0), "r"(b1));
}

// ====== Pure-fp16 GEMM mainloop: CTA 128x128, BK=64, warp tile 32x64 ======
// warps 4 (M) x 2 (N). Stage: A 16K + B 16K = 32KB; 3-stage pipeline
// (96KB/CTA, 2 CTAs/SM = 192KB). Row = 128B (8 chunks), SW128: phys ch = ch^(row&7).
#define STAGE_BYTES 32768
#define NSTAGES_BUF 3
#define SMEM_BYTES (NSTAGES_BUF * STAGE_BYTES)
#define OFF_A 0
#define OFF_B 16384

// ldv = K/8 (uint4 stride). k0v = stage*8 (64 halves = 8 uint4).
__device__ __forceinline__ void prefetch_stage(
    uint32_t sbase,
    const uint4* __restrict__ A, const uint4* __restrict__ B,
    int ldv, int k0v)
{
    const int tid = threadIdx.x;
#pragma unroll
    for (int i = 0; i < 4; i++) {
        int c = tid + i * 256;               // 0..1023
        int row = c >> 3, ch = c & 7;
        uint32_t so = (uint32_t)(row * 128 + ((ch ^ (row & 7)) << 4));
        size_t go = (size_t)row * ldv + k0v + ch;
        cp16(sbase + OFF_A + so, A + go);
        cp16(sbase + OFF_B + so, B + go);
    }
    asm volatile("cp.async.commit_group;" ::: "memory");
}

// acc[2][8][4]: mt in {0,1} (16-row tiles), nt in {0..7} (8-col tiles)
__device__ __forceinline__ void mma_mainloop(
    const uint4* __restrict__ A, const uint4* __restrict__ B,
    int ldv, int nStages, uint32_t smb, float acc[2][8][4])
{
    const int lane = threadIdx.x & 31;
    const int wid  = threadIdx.x >> 5;
    const int warp_m = wid & 3;        // 4 m-groups of 32 rows
    const int warp_n = wid >> 2;       // 2 n-groups of 64 cols
    const int r8 = lane & 7;

    const int aro = ((lane >> 3) & 1) * 8 + r8;   // A: row within m16
    const int acs = lane >> 4;                    // A: chunk select (0/1)
    const int bro = (lane >> 4) * 8 + r8;         // B: row within n16
    const int bcs = (lane >> 3) & 1;              // B: chunk select (0/1)

    int arow[2], aswz[2];
#pragma unroll
    for (int mt = 0; mt < 2; mt++) {
        arow[mt] = warp_m * 32 + mt * 16 + aro;
        aswz[mt] = arow[mt] & 7;
    }
    int brow[4], bswz[4];
#pragma unroll
    for (int np = 0; np < 4; np++) {
        brow[np] = warp_n * 64 + np * 16 + bro;
        bswz[np] = brow[np] & 7;
    }

    prefetch_stage(smb + 0 * STAGE_BYTES, A, B, ldv, 0);
    prefetch_stage(smb + 1 * STAGE_BYTES, A, B, ldv, 8);

    for (int s = 0; s < nStages; s++) {
        asm volatile("cp.async.wait_group 1;" ::: "memory");
        __syncthreads();

        if (s + 2 < nStages)
            prefetch_stage(smb + ((s + 2) % NSTAGES_BUF) * STAGE_BYTES, A, B, ldv, (s + 2) * 8);
        else
            asm volatile("cp.async.commit_group;" ::: "memory");

        uint32_t st = smb + (s % NSTAGES_BUF) * STAGE_BYTES;

        uint32_t bfr[4][4];   // B frags for current ks
        uint32_t ab[2][4];    // double-buffered A frags

        // B frags for ks=0
#pragma unroll
        for (int np = 0; np < 4; np++) {
            uint32_t bo = (uint32_t)(brow[np] * 128 + ((bcs ^ bswz[np]) << 4));
            ldm4(bfr[np], st + OFF_B + bo);
        }
        // A frag for step 0 (ks=0, mt=0)
        {
            uint32_t ao = (uint32_t)(arow[0] * 128 + ((acs ^ aswz[0]) << 4));
            ldm4(ab[0], st + OFF_A + ao);
        }

        // 8 steps: i -> ks = i>>1 (k16-pair), mt = i&1 ; 8 MMAs per step
#pragma unroll
        for (int i = 0; i < 8; i++) {
            const int cur = i & 1;
            if (i && (i & 1) == 0) {
                const int ks = i >> 1;
#pragma unroll
                for (int np = 0; np < 4; np++) {
                    uint32_t bo = (uint32_t)(brow[np] * 128 + (((ks * 2 + bcs) ^ bswz[np]) << 4));
                    ldm4(bfr[np], st + OFF_B + bo);
                }
            }
            if (i < 7) {
                const int ni = i + 1;
                const int nks = ni >> 1, nmt = ni & 1;
                uint32_t ao = (uint32_t)(arow[nmt] * 128 + (((nks * 2 + acs) ^ aswz[nmt]) << 4));
                ldm4(ab[ni & 1], st + OFF_A + ao);
            }
            const int mt = i & 1;
            const uint32_t* a = ab[cur];
#pragma unroll
            for (int nt = 0; nt < 8; nt++)
                mma16816(acc[mt][nt], a, bfr[nt >> 1][(nt & 1) * 2], bfr[nt >> 1][(nt & 1) * 2 + 1]);
        }
    }
}

// GEMM1: h[:, z*512 + bx*128 ..] = x_sel[z] @ Wc[z]^T + bc ; emits fp16
__global__ __launch_bounds__(256, 2) void gemm1_kernel(const float* __restrict__ bc) {
    extern __shared__ char sm[];
    uint32_t smb = smem_u32(sm);
    const int bx = blockIdx.x, by = blockIdx.y, z = blockIdx.z;
    const int chunk = g_topk[z];

    const uint4* A = (const uint4*)(g_x16 + (size_t)z * BSZ * CIN + (size_t)by * 128 * CIN);
    const uint4* B = (const uint4*)(g_wc + (size_t)z * COUT * CIN + (size_t)bx * 128 * CIN);

    float acc[2][8][4];
#pragma unroll
    for (int a = 0; a < 2; a++)
#pragma unroll
        for (int b = 0; b < 8; b++)
#pragma unroll
            for (int c = 0; c < 4; c++) acc[a][b][c] = 0.0f;

    mma_mainloop(A, B, CIN / 8, CIN / 64, smb, acc);

    const int lane = threadIdx.x & 31, wid = threadIdx.x >> 5;
    const int warp_m = wid & 3, warp_n = wid >> 2;
    const int g = lane >> 2, tg = lane & 3;
#pragma unroll
    for (int mt = 0; mt < 2; mt++) {
#pragma unroll
        for (int nt = 0; nt < 8; nt++) {
            int cl = warp_n * 64 + nt * 8 + tg * 2;
            int colg = z * COUT + bx * 128 + cl;
            float b0 = __ldg(bc + (size_t)chunk * COUT + bx * 128 + cl);
            float b1 = __ldg(bc + (size_t)chunk * COUT + bx * 128 + cl + 1);
#pragma unroll
            for (int half = 0; half < 2; half++) {
                int row = by * 128 + warp_m * 32 + mt * 16 + g + half * 8;
                float v0 = acc[mt][nt][half * 2 + 0] + b0;
                float v1 = acc[mt][nt][half * 2 + 1] + b1;
                size_t o = (size_t)row * HID + colg;
                *(ushort2*)(g_h16 + o) = make_ushort2(
                    __half_as_ushort(__float2half_rn(v0)),
                    __half_as_ushort(__float2half_rn(v1)));
            }
        }
    }
}

// GEMM2: out = h @ W_final + b_final (CTA 128x128, grid 32x32)
__global__ __launch_bounds__(256, 2) void gemm2_kernel(const float* __restrict__ bf,
                                                       float* __restrict__ out) {
    extern __shared__ char sm[];
    uint32_t smb = smem_u32(sm);
    const int bx = blockIdx.x, by = blockIdx.y;

    const uint4* A = (const uint4*)(g_h16 + (size_t)by * 128 * HID);
    const uint4* B = (const uint4*)(g_wf + (size_t)bx * 128 * HID);

    float acc[2][8][4];
#pragma unroll
    for (int a = 0; a < 2; a++)
#pragma unroll
        for (int b = 0; b < 8; b++)
#pragma unroll
            for (int c = 0; c < 4; c++) acc[a][b][c] = 0.0f;

    mma_mainloop(A, B, HID / 8, HID / 64, smb, acc);

    const int lane = threadIdx.x & 31, wid = threadIdx.x >> 5;
    const int warp_m = wid & 3, warp_n = wid >> 2;
    const int g = lane >> 2, tg = lane & 3;
#pragma unroll
    for (int mt = 0; mt < 2; mt++) {
#pragma unroll
        for (int nt = 0; nt < 8; nt++) {
            int col = bx * 128 + warp_n * 64 + nt * 8 + tg * 2;
            float b0 = __ldg(bf + col);
            float b1 = __ldg(bf + col + 1);
#pragma unroll
            for (int half = 0; half < 2; half++) {
                int row = by * 128 + warp_m * 32 + mt * 16 + g + half * 8;
                float2 v;
                v.x = acc[mt][nt][half * 2 + 0] + b0;
                v.y = acc[mt][nt][half * 2 + 1] + b1;
                *(float2*)(out + (size_t)row * OUTF + col) = v;
            }
        }
    }
}

// ---------------- launcher ----------------
extern "C" void kernel_launch(void* const* d_in, const int* in_sizes, int n_in,
                              void* d_out, int out_size)
{
    const float* x  = (const float*)d_in[0];
    const float* Wc = (const float*)d_in[1];
    const float* bc = (const float*)d_in[2];
    const float* Wf = (const float*)d_in[3];
    const float* bf = (const float*)d_in[4];
    float* out = (float*)d_out;

    cudaFuncSetAttribute(gemm1_kernel, cudaFuncAttributeMaxDynamicSharedMemorySize, SMEM_BYTES);
    cudaFuncSetAttribute(gemm2_kernel, cudaFuncAttributeMaxDynamicSharedMemorySize, SMEM_BYTES);

    activity_kernel<<<2048, 256>>>(x);                 // 1 (topk fused)
    convert_all_kernel<<<CVT_TOTAL, 256>>>(x, Wc, Wf); // 2
    gemm1_kernel<<<dim3(4, 32, 2), 256, SMEM_BYTES>>>(bc);        // 3
    gemm2_kernel<<<dim3(32, 32), 256, SMEM_BYTES>>>(bf, out);     // 4
}